// round 12
// baseline (speedup 1.0000x reference)
#include <cuda_runtime.h>
#include <math.h>

#define NUM_INITS   64
#define BATCH_N     128
#define TOTAL_P     18378
#define OFF_W1      0
#define OFF_B1      400
#define OFF_W2      416
#define OFF_B2      13216
#define OFF_WD      13248
#define OFF_BD      18368

// a1 padded layout: [img][ci][row(12) x stride 20]
#define A1_RS   20
#define A1_CS   240          // 12 rows * 20
#define A1_IS   3840         // 16 ch * 240

#define WPAD    101          // per-c2 weight chunk stride (101 = 5 mod 32, conflict-free)

__global__ __launch_bounds__(256, 3)
void ensemble_lenet_kernel(const float* __restrict__ params,
                           const float* __restrict__ batch,
                           float* __restrict__ out)
{
    __shared__ float s_w1[400];
    __shared__ float s_b1[16];
    __shared__ float s_b2[32];
    __shared__ __align__(16) float s_a1[2 * A1_IS];   // 7680 fl; reused as reduce scratch
    __shared__ __align__(16) float s_u[32 * WPAD];    // union: img(1568) / w2 chunk(3232)
    __shared__ __align__(16) float s_a2[2][512];      // transposed: [pos16][c2]
    __shared__ float s_dot[2][16];

    const int blk   = blockIdx.x;
    const int init  = blk >> 6;
    const int npair = blk & 63;
    const int t     = threadIdx.x;
    const int img   = t >> 7;        // 0,1
    const int tl    = t & 127;

    const float* __restrict__ P = params + init * TOTAL_P;

    // ---------- stage 2 images (contiguous) + conv1 params ----------
    {
        const float* ib = batch + (npair * 2) * 784;
        for (int idx = t; idx < 1568; idx += 256) s_u[idx] = ib[idx];
        for (int idx = t; idx < 400;  idx += 256) s_w1[idx] = P[idx];
        if (t < 16) s_b1[t] = P[OFF_B1 + t];
        if (t < 32) s_b2[t] = P[OFF_B2 + t];
    }
    __syncthreads();

    // ---------- conv1 + relu + pool (unchanged, known-good) ----------
    {
        const int co = (tl >> 3) & 15;
        const int l8 = tl & 7;
        float w1r[25];
        #pragma unroll
        for (int q = 0; q < 25; q++) w1r[q] = s_w1[co * 25 + q];
        const float b1 = s_b1[co];
        const float* imgp = s_u + img * 784;
        float* a1p = s_a1 + img * A1_IS + co * A1_CS;

        #pragma unroll 2
        for (int k = 0; k < 18; k++) {
            const int idx = l8 + (k << 3);       // 0..143
            const int py = idx / 12;
            const int px = idx - py * 12;
            const int iy = py * 2, ix = px * 2;

            float a00 = b1, a01 = b1, a10 = b1, a11 = b1;
            #pragma unroll
            for (int r = 0; r < 6; r++) {
                const float2* rp = (const float2*)(imgp + (iy + r) * 28 + ix);
                const float2 v0 = rp[0], v1 = rp[1], v2 = rp[2];
                float row[6];
                row[0]=v0.x; row[1]=v0.y; row[2]=v1.x; row[3]=v1.y; row[4]=v2.x; row[5]=v2.y;
                if (r < 5) {
                    #pragma unroll
                    for (int dx = 0; dx < 5; dx++) {
                        const float w = w1r[r * 5 + dx];
                        a00 = fmaf(row[dx],     w, a00);
                        a01 = fmaf(row[dx + 1], w, a01);
                    }
                }
                if (r >= 1) {
                    #pragma unroll
                    for (int dx = 0; dx < 5; dx++) {
                        const float w = w1r[(r - 1) * 5 + dx];
                        a10 = fmaf(row[dx],     w, a10);
                        a11 = fmaf(row[dx + 1], w, a11);
                    }
                }
            }
            const float m = fmaxf(fmaxf(a00, a01), fmaxf(a10, a11));
            a1p[py * A1_RS + px] = fmaxf(m, 0.0f);
        }
    }
    __syncthreads();

    // ---------- conv2: lane = c2 (32 channels), broadcast activations ----------
    // 4 warps per image: wimg = tl>>5; half = wimg&1 (ci even-pairs / odd-pairs
    // within each 4-ci chunk); rowgrp = wimg>>1 (output rows 0-3 / 4-7).
    const int wimg   = tl >> 5;
    const int half   = wimg & 1;
    const int rowgrp = wimg >> 1;
    const int c2     = tl & 31;
    const int y0     = rowgrp * 4;

    float acc[32];
    {
        const float binit = (half == 0) ? s_b2[c2] : 0.0f;
        #pragma unroll
        for (int k = 0; k < 32; k++) acc[k] = binit;
    }

    for (int cb = 0; cb < 4; cb++) {
        // stage weight chunk: s_u[c*WPAD + ciL*25 + tap] = w2[c][4cb+ciL][tap]
        // gmem reads are 100-float contiguous runs per c2 (coalesced).
        for (int idx = t; idx < 3200; idx += 256) {
            const int c   = idx / 100;
            const int rem = idx - c * 100;
            s_u[c * WPAD + rem] = P[OFF_W2 + c * 400 + cb * 100 + rem];
        }
        __syncthreads();

        #pragma unroll
        for (int cc = 0; cc < 2; cc++) {
            const int ciL = half * 2 + cc;                 // 0..3
            const float* ap = s_a1 + img * A1_IS + (cb * 4 + ciL) * A1_CS;

            float wv[25];                                  // lane-distinct, conflict-free
            #pragma unroll
            for (int q = 0; q < 25; q++) wv[q] = s_u[c2 * WPAD + ciL * 25 + q];

            #pragma unroll
            for (int r = 0; r < 8; r++) {                  // input row y0+r
                #pragma unroll
                for (int c = 0; c < 12; c++) {
                    const float av = ap[(y0 + r) * A1_RS + c];   // broadcast LDS
                    #pragma unroll
                    for (int yl = 0; yl < 4; yl++) {
                        if (yl <= r && r - yl <= 4) {
                            #pragma unroll
                            for (int x = 0; x < 8; x++) {
                                if (x <= c && c - x <= 4) {
                                    acc[yl * 8 + x] =
                                        fmaf(av, wv[(r - yl) * 5 + (c - x)], acc[yl * 8 + x]);
                                }
                            }
                        }
                    }
                }
            }
        }
        __syncthreads();
    }

    // ---------- cross-half reduction (scratch overlays s_a1) + pool ----------
    {
        float* scr = s_a1 + ((img * 2 + rowgrp) * 32) * 32 + c2;
        if (half == 1) {
            #pragma unroll
            for (int k = 0; k < 32; k++) scr[k * 32] = acc[k];   // conflict-free
        }
        __syncthreads();
        if (half == 0) {
            #pragma unroll
            for (int k = 0; k < 32; k++) acc[k] += scr[k * 32];
            // relu + 2x2 maxpool -> a2 transposed [pos16][c2]
            #pragma unroll
            for (int pyL = 0; pyL < 2; pyL++) {
                #pragma unroll
                for (int px = 0; px < 4; px++) {
                    const float m = fmaxf(
                        fmaxf(acc[(pyL*2)*8 + px*2],     acc[(pyL*2)*8 + px*2 + 1]),
                        fmaxf(acc[(pyL*2+1)*8 + px*2],   acc[(pyL*2+1)*8 + px*2 + 1]));
                    s_a2[img][((rowgrp * 2 + pyL) * 4 + px) * 32 + c2] = fmaxf(m, 0.0f);
                }
            }
        }
    }
    __syncthreads();

    // ---------- dense 512 -> 10 ----------
    // Warp-uniform. thread: o = tl>>3 (clamped), l = tl&7 owns contiguous
    // f = l*64 .. l*64+63. a2 transposed addr = (f&15)*32 + (f>>4): 8 distinct
    // stride-4 banks, 4-way o-broadcast -> conflict-free.
    {
        const int o  = tl >> 3;               // 0..15
        const int oc = (o < 10) ? o : 9;
        const int l  = tl & 7;
        const float2* wr2 = (const float2*)(P + OFF_WD + oc * 512 + l * 64);
        const float* a2 = s_a2[img];
        float partial = 0.0f;
        #pragma unroll
        for (int i2 = 0; i2 < 32; i2++) {
            const float2 w = wr2[i2];
            const int f0 = l * 64 + i2 * 2;
            partial = fmaf(w.x, a2[((f0    ) & 15) * 32 + ((f0    ) >> 4)], partial);
            partial = fmaf(w.y, a2[((f0 + 1) & 15) * 32 + ((f0 + 1) >> 4)], partial);
        }
        #pragma unroll
        for (int off = 4; off; off >>= 1)
            partial += __shfl_down_sync(0xFFFFFFFFu, partial, off, 8);
        if (l == 0 && o < 10) s_dot[img][o] = partial + P[OFF_BD + o];
    }
    __syncthreads();

    // ---------- log_softmax over 10, write out ----------
    if (t < 64) {
        const int im = t >> 5;
        const int lane = t & 31;
        const float v = (lane < 10) ? s_dot[im][lane] : -INFINITY;
        float mx = v;
        #pragma unroll
        for (int off = 16; off; off >>= 1)
            mx = fmaxf(mx, __shfl_xor_sync(0xFFFFFFFFu, mx, off));
        const float e = (lane < 10) ? __expf(v - mx) : 0.0f;
        float s = e;
        #pragma unroll
        for (int off = 16; off; off >>= 1)
            s += __shfl_xor_sync(0xFFFFFFFFu, s, off);
        if (lane < 10) {
            const int n = npair * 2 + im;
            out[(init * BATCH_N + n) * 10 + lane] = v - mx - __logf(s);
        }
    }
}

extern "C" void kernel_launch(void* const* d_in, const int* in_sizes, int n_in,
                              void* d_out, int out_size)
{
    const float* params = (const float*)d_in[0];
    const float* batch  = (const float*)d_in[1];
    if (n_in >= 2 && in_sizes[0] != NUM_INITS * TOTAL_P) {
        params = (const float*)d_in[1];
        batch  = (const float*)d_in[0];
    }
    float* out = (float*)d_out;
    ensemble_lenet_kernel<<<NUM_INITS * (BATCH_N / 2), 256>>>(params, batch, out);
}